// round 9
// baseline (speedup 1.0000x reference)
#include <cuda_runtime.h>

// Langevin_2439541424651 — 131072 independent 200-step scalar recurrences.
// HBM-bound: ~100MB read + ~301MB write. R5/R7/R8 all plateau at ~5.2TB/s
// regardless of MLP/width => DRAM-mix limited. This round: batch stores by
// tensor in 4-step groups (4KB contiguous bursts per stream per block)
// instead of rotating x/y/out every step, to improve DRAM row locality.

#define N_PART 1024
#define DX     128
#define STEPS  200
#define KB     4
#define ND     (N_PART * DX)                      // 131072 threads
#define TOT_XT ((long)N_PART * STEPS * DX)

__global__ void __launch_bounds__(256) langevin_kernel(
    const float* __restrict__ x0,      // [N, DX]
    const float* __restrict__ y0,      // [N, DX]
    const float* __restrict__ mean,    // [DX]
    const float* __restrict__ var,     // [DX]
    const float* __restrict__ gammas,  // [STEPS]
    const float* __restrict__ noise,   // [STEPS, N, DX]
    float* __restrict__ x_tot,         // [N, STEPS, DX]
    float* __restrict__ y_tot,
    float* __restrict__ out,
    float* __restrict__ steps_out)     // [N, STEPS]
{
    __shared__ float s_g[STEPS];
    __shared__ float s_s[STEPS];

    for (int k = threadIdx.x; k < STEPS; k += blockDim.x) {
        float g = gammas[k];
        s_g[k] = g;
        s_s[k] = sqrtf(2.0f * g);
    }

    int tid = blockIdx.x * blockDim.x + threadIdx.x;   // 0 .. ND-1

    // Steps tensor [N, STEPS, 1]: coalesced prologue, no tail kernel.
    for (int i = tid; i < N_PART * STEPS; i += ND)
        steps_out[i] = (float)(i % STEPS);

    __syncthreads();

    int d = tid & (DX - 1);
    int n = tid >> 7;

    float x  = x0[tid];
    float yv = y0[tid];
    float m  = mean[d];
    float iv = 1.0f / var[d];

    long base = (long)n * STEPS * DX + d;
    const float* __restrict__ zp = noise + tid;

    // t_old = x - c*(x-m);  x_new = t_old + s*z
    // t_old - t_new = (t_old - x_new) + c*(x_new - m),  c = gamma/var
    for (int kb = 0; kb < STEPS; kb += KB) {
        float zb[KB], xnb[KB], dfb[KB];

#pragma unroll
        for (int j = 0; j < KB; ++j)
            zb[j] = zp[(long)(kb + j) * ND];

#pragma unroll
        for (int j = 0; j < KB; ++j) {
            int k = kb + j;
            float g = s_g[k];
            float s = s_s[k];

            float c     = g * iv;
            float t_old = fmaf(-c, x - m, x);
            float xn    = fmaf(s, zb[j], t_old);
            dfb[j] = fmaf(c, xn - m, t_old - xn);
            xnb[j] = xn;
            x = xn;
        }

        long o = base + (long)kb * DX;
#pragma unroll
        for (int j = 0; j < KB; ++j)
            x_tot[o + (long)j * DX] = xnb[j];
#pragma unroll
        for (int j = 0; j < KB; ++j)
            y_tot[o + (long)j * DX] = yv;
#pragma unroll
        for (int j = 0; j < KB; ++j)
            out[o + (long)j * DX] = dfb[j];
    }
}

extern "C" void kernel_launch(void* const* d_in, const int* in_sizes, int n_in,
                              void* d_out, int out_size)
{
    const float* x0     = (const float*)d_in[0];
    const float* y0     = (const float*)d_in[1];
    const float* mean   = (const float*)d_in[2];
    const float* var    = (const float*)d_in[3];
    const float* gammas = (const float*)d_in[4];
    const float* noise  = (const float*)d_in[5];

    float* base  = (float*)d_out;
    float* x_tot = base;                 // [N, S, D]
    float* y_tot = base + TOT_XT;
    float* outp  = base + 2 * TOT_XT;
    float* steps = base + 3 * TOT_XT;    // [N, S, 1]

    langevin_kernel<<<ND / 256, 256>>>(x0, y0, mean, var, gammas, noise,
                                       x_tot, y_tot, outp, steps);
}

// round 10
// speedup vs baseline: 1.1818x; 1.1818x over previous
#include <cuda_runtime.h>

// Langevin_2439541424651 — 131072 independent 200-step scalar recurrences.
// HBM-bound. Phase-split experiment: y_tot (pure replication, 100MB) written
// as a phase-1 flat sequential float4 burst (best DRAM row locality, source
// y0 is L2-resident); phase-2 is the proven R5 loop with a leaner 1R:2W mix.
// Plain cached ld/st throughout (.cs regresses on GB300: R3/R4 evidence).

#define N_PART 1024
#define DX     128
#define STEPS  200
#define ND     (N_PART * DX)                      // 131072 threads
#define TOT_XT ((long)N_PART * STEPS * DX)        // 26,214,400
#define YF4    (TOT_XT / 4)                       // 6,553,600 float4s

__global__ void __launch_bounds__(256) langevin_kernel(
    const float*  __restrict__ x0,      // [N, DX]
    const float4* __restrict__ y04,     // [N, DX/4]
    const float*  __restrict__ mean,    // [DX]
    const float*  __restrict__ var,     // [DX]
    const float*  __restrict__ gammas,  // [STEPS]
    const float*  __restrict__ noise,   // [STEPS, N, DX]
    float*  __restrict__ x_tot,         // [N, STEPS, DX]
    float4* __restrict__ y_tot4,        // [N, STEPS, DX/4]
    float*  __restrict__ out,           // [N, STEPS, DX]
    float*  __restrict__ steps_out)     // [N, STEPS]
{
    __shared__ float s_g[STEPS];
    __shared__ float s_s[STEPS];

    for (int k = threadIdx.x; k < STEPS; k += blockDim.x) {
        float g = gammas[k];
        s_g[k] = g;
        s_s[k] = sqrtf(2.0f * g);
    }

    int tid = blockIdx.x * blockDim.x + threadIdx.x;   // 0 .. ND-1

    // ---- Phase 1a: steps tensor [N, STEPS] (0.8MB, coalesced) ----
    for (int i = tid; i < N_PART * STEPS; i += ND)
        steps_out[i] = (float)(i % STEPS);

    // ---- Phase 1b: y_tot replication as pure sequential float4 writes ----
    // Flat float4 index f over [n][k][d4]: d4 = f & 31, row n = (f>>5)/STEPS.
    // Source y04[n*32 + d4] is 512KB -> L2-resident after first touch.
#pragma unroll 2
    for (long f = tid; f < YF4; f += ND) {
        int d4 = (int)f & 31;
        int n  = (int)(f >> 5) / STEPS;
        y_tot4[f] = y04[n * 32 + d4];
    }

    __syncthreads();

    // ---- Phase 2: Langevin recurrence (1 read : 2 write streams) ----
    int d = tid & (DX - 1);
    int n = tid >> 7;

    float x  = x0[tid];
    float m  = mean[d];
    float iv = 1.0f / var[d];

    long base = (long)n * STEPS * DX + d;
    const float* __restrict__ zp = noise + tid;

    // t_old = x - c*(x-m);  x_new = t_old + s*z
    // t_old - t_new = (t_old - x_new) + c*(x_new - m),  c = gamma/var
#pragma unroll 8
    for (int k = 0; k < STEPS; ++k) {
        float g = s_g[k];
        float s = s_s[k];
        float z = zp[(long)k * ND];

        float c     = g * iv;
        float t_old = fmaf(-c, x - m, x);
        float xn    = fmaf(s, z, t_old);
        float diff  = fmaf(c, xn - m, t_old - xn);
        x = xn;

        long o = base + (long)k * DX;
        x_tot[o] = xn;
        out[o]   = diff;
    }
}

extern "C" void kernel_launch(void* const* d_in, const int* in_sizes, int n_in,
                              void* d_out, int out_size)
{
    const float* x0     = (const float*)d_in[0];
    const float* y0     = (const float*)d_in[1];
    const float* mean   = (const float*)d_in[2];
    const float* var    = (const float*)d_in[3];
    const float* gammas = (const float*)d_in[4];
    const float* noise  = (const float*)d_in[5];

    float* base  = (float*)d_out;
    float* x_tot = base;                 // [N, S, D]
    float* y_tot = base + TOT_XT;
    float* outp  = base + 2 * TOT_XT;
    float* steps = base + 3 * TOT_XT;    // [N, S, 1]

    langevin_kernel<<<ND / 256, 256>>>(
        x0, (const float4*)y0, mean, var, gammas, noise,
        x_tot, (float4*)y_tot, outp, steps);
}

// round 11
// speedup vs baseline: 1.2494x; 1.0571x over previous
#include <cuda_runtime.h>

// Langevin_2439541424651 — 131072 independent 200-step scalar recurrences.
// HBM-bound: ~100MB read + ~301MB write. Exactly the R5 champion kernel
// (plain cached ld/st, scalar, unroll-8, steps folded) with ONE change:
// 128-thread blocks -> 1024 CTAs -> 6.92 CTAs/SM (1.2% imbalance) instead
// of 512x256 -> 3.46 CTAs/SM (a 4-vs-3 CTA, ~16% per-SM work imbalance).

#define N_PART 1024
#define DX     128
#define STEPS  200
#define ND     (N_PART * DX)                      // 131072 threads
#define TOT_XT ((long)N_PART * STEPS * DX)

__global__ void __launch_bounds__(128) langevin_kernel(
    const float* __restrict__ x0,      // [N, DX]
    const float* __restrict__ y0,      // [N, DX]
    const float* __restrict__ mean,    // [DX]
    const float* __restrict__ var,     // [DX]
    const float* __restrict__ gammas,  // [STEPS]
    const float* __restrict__ noise,   // [STEPS, N, DX]
    float* __restrict__ x_tot,         // [N, STEPS, DX]
    float* __restrict__ y_tot,
    float* __restrict__ out,
    float* __restrict__ steps_out)     // [N, STEPS]
{
    __shared__ float s_g[STEPS];
    __shared__ float s_s[STEPS];

    for (int k = threadIdx.x; k < STEPS; k += blockDim.x) {
        float g = gammas[k];
        s_g[k] = g;
        s_s[k] = sqrtf(2.0f * g);
    }

    int tid = blockIdx.x * blockDim.x + threadIdx.x;   // 0 .. ND-1

    // Steps tensor [N, STEPS, 1]: coalesced prologue, no tail kernel.
    for (int i = tid; i < N_PART * STEPS; i += ND)
        steps_out[i] = (float)(i % STEPS);

    __syncthreads();

    int d = tid & (DX - 1);
    int n = tid >> 7;

    float x  = x0[tid];
    float yv = y0[tid];
    float m  = mean[d];
    float iv = 1.0f / var[d];

    long base = (long)n * STEPS * DX + d;
    const float* __restrict__ zp = noise + tid;

    // t_old = x - c*(x-m);  x_new = t_old + s*z
    // t_old - t_new = (t_old - x_new) + c*(x_new - m),  c = gamma/var
#pragma unroll 8
    for (int k = 0; k < STEPS; ++k) {
        float g = s_g[k];
        float s = s_s[k];
        float z = zp[(long)k * ND];

        float c     = g * iv;
        float t_old = fmaf(-c, x - m, x);
        float xn    = fmaf(s, z, t_old);
        float diff  = fmaf(c, xn - m, t_old - xn);
        x = xn;

        long o = base + (long)k * DX;
        x_tot[o] = xn;
        y_tot[o] = yv;
        out[o]   = diff;
    }
}

extern "C" void kernel_launch(void* const* d_in, const int* in_sizes, int n_in,
                              void* d_out, int out_size)
{
    const float* x0     = (const float*)d_in[0];
    const float* y0     = (const float*)d_in[1];
    const float* mean   = (const float*)d_in[2];
    const float* var    = (const float*)d_in[3];
    const float* gammas = (const float*)d_in[4];
    const float* noise  = (const float*)d_in[5];

    float* base  = (float*)d_out;
    float* x_tot = base;                 // [N, S, D]
    float* y_tot = base + TOT_XT;
    float* outp  = base + 2 * TOT_XT;
    float* steps = base + 3 * TOT_XT;    // [N, S, 1]

    langevin_kernel<<<ND / 128, 128>>>(x0, y0, mean, var, gammas, noise,
                                       x_tot, y_tot, outp, steps);
}